// round 3
// baseline (speedup 1.0000x reference)
#include <cuda_runtime.h>
#include <cstdint>

#define NN 65536
#define HH 128
#define EE 524288

// ---------------- static scratch ----------------
__device__ int   g_deg[3][NN];
__device__ int   g_rowptr[3][NN + 1];
__device__ int   g_cursor[3][NN];
__device__ int   g_col[3][EE];
__device__ float g_h[3][NN * HH];   // 0: A = pf@Wr1^T, 1: B = rf@Wr2^T, 2: C = rf@Wp^T

// ---------------- CSR build ----------------
__global__ void k_hist(const int* __restrict__ pass_dst,
                       const int* __restrict__ connect_dst,
                       const int* __restrict__ transfer_dst) {
    int i = blockIdx.x * blockDim.x + threadIdx.x;
    if (i >= 3 * EE) return;
    int r = i / EE, e = i - r * EE;
    const int* dst = (r == 0) ? pass_dst : (r == 1) ? connect_dst : transfer_dst;
    atomicAdd(&g_deg[r][dst[e]], 1);
}

__global__ void k_scan() {
    const int CH = NN / 1024;
    int r = blockIdx.x;
    int t = threadIdx.x;
    int base = t * CH;
    int s = 0;
    for (int j = 0; j < CH; j++) s += g_deg[r][base + j];

    __shared__ int sm[1024];
    sm[t] = s;
    __syncthreads();
    for (int off = 1; off < 1024; off <<= 1) {
        int v = (t >= off) ? sm[t - off] : 0;
        __syncthreads();
        sm[t] += v;
        __syncthreads();
    }
    int run = sm[t] - s;
    for (int j = 0; j < CH; j++) {
        g_rowptr[r][base + j] = run;
        g_cursor[r][base + j] = run;
        run += g_deg[r][base + j];
    }
    if (t == 1023) g_rowptr[r][NN] = run;
}

__global__ void k_fill(const int* __restrict__ pass_src, const int* __restrict__ pass_dst,
                       const int* __restrict__ connect_src, const int* __restrict__ connect_dst,
                       const int* __restrict__ transfer_src, const int* __restrict__ transfer_dst) {
    int i = blockIdx.x * blockDim.x + threadIdx.x;
    if (i >= 3 * EE) return;
    int r = i / EE, e = i - r * EE;
    const int *src, *dst;
    if (r == 0)      { src = pass_src;     dst = pass_dst; }
    else if (r == 1) { src = connect_src;  dst = connect_dst; }
    else             { src = transfer_src; dst = transfer_dst; }
    int d = dst[e];
    int pos = atomicAdd(&g_cursor[r][d], 1);
    g_col[r][pos] = src[e];
}

// ---------------- tf32 tensor-core plain GEMM: Y[i][j] = sum_k X[i][k]*W[j][k] ----------------
__device__ __forceinline__ uint32_t f2tf32(float x) {
    uint32_t r;
    asm("cvt.rna.tf32.f32 %0, %1;" : "=r"(r) : "f"(x));
    return r;
}

__device__ __forceinline__ void mma_tf32(float* d, const uint32_t* a, const uint32_t* b) {
    asm volatile(
        "mma.sync.aligned.m16n8k8.row.col.f32.tf32.tf32.f32 "
        "{%0,%1,%2,%3},{%4,%5,%6,%7},{%8,%9},{%0,%1,%2,%3};"
        : "+f"(d[0]), "+f"(d[1]), "+f"(d[2]), "+f"(d[3])
        : "r"(a[0]), "r"(a[1]), "r"(a[2]), "r"(a[3]), "r"(b[0]), "r"(b[1]));
}

#define KC 64
#define XS 68   // padded smem stride (in 4B words)

template<int LDW>
__global__ void __launch_bounds__(256, 2) k_gemm_plain(const float* __restrict__ X,
                                                       const float* __restrict__ W,
                                                       float* __restrict__ Y) {
    extern __shared__ uint32_t smemU[];
    uint32_t* sX = smemU;                 // [128][XS] tf32 bits
    uint32_t* sW = smemU + 128 * XS;

    const int t = threadIdx.x;
    const int warp = t >> 5, lane = t & 31;
    const int g = lane >> 2, tg = lane & 3;
    const int mw = (warp & 3) * 32;
    const int nw = (warp >> 2) * 64;
    const int row0 = blockIdx.x * 128;

    float acc[2][8][4];
    #pragma unroll
    for (int i = 0; i < 2; i++)
        #pragma unroll
        for (int j = 0; j < 8; j++)
            #pragma unroll
            for (int q = 0; q < 4; q++) acc[i][j][q] = 0.f;

    #pragma unroll
    for (int c = 0; c < HH / KC; c++) {
        __syncthreads();
        #pragma unroll
        for (int it = 0; it < 8; it++) {
            int idx = it * 256 + t;          // 2048 float4 per buffer
            int row = idx >> 4, c4 = idx & 15;
            float4 xv = __ldg((const float4*)(X + (size_t)(row0 + row) * HH + c * KC) + c4);
            uint32_t* dx = &sX[row * XS + c4 * 4];
            dx[0] = f2tf32(xv.x); dx[1] = f2tf32(xv.y); dx[2] = f2tf32(xv.z); dx[3] = f2tf32(xv.w);
            float4 wv = __ldg((const float4*)(W + (size_t)row * LDW + c * KC) + c4);
            uint32_t* dw = &sW[row * XS + c4 * 4];
            dw[0] = f2tf32(wv.x); dw[1] = f2tf32(wv.y); dw[2] = f2tf32(wv.z); dw[3] = f2tf32(wv.w);
        }
        __syncthreads();

        #pragma unroll
        for (int ks = 0; ks < KC / 8; ks++) {
            int k0 = ks * 8;
            uint32_t a[2][4], b[8][2];
            #pragma unroll
            for (int i = 0; i < 2; i++) {
                int r = mw + i * 16 + g;
                a[i][0] = sX[r * XS + k0 + tg];
                a[i][1] = sX[(r + 8) * XS + k0 + tg];
                a[i][2] = sX[r * XS + k0 + tg + 4];
                a[i][3] = sX[(r + 8) * XS + k0 + tg + 4];
            }
            #pragma unroll
            for (int j = 0; j < 8; j++) {
                int n = nw + j * 8 + g;
                b[j][0] = sW[n * XS + k0 + tg];
                b[j][1] = sW[n * XS + k0 + tg + 4];
            }
            #pragma unroll
            for (int i = 0; i < 2; i++)
                #pragma unroll
                for (int j = 0; j < 8; j++)
                    mma_tf32(acc[i][j], a[i], b[j]);
        }
    }

    #pragma unroll
    for (int j = 0; j < 8; j++) {
        int col = nw + j * 8 + 2 * tg;
        #pragma unroll
        for (int i = 0; i < 2; i++) {
            int ra = row0 + mw + i * 16 + g;
            *(float2*)(Y + (size_t)ra * HH + col)       = make_float2(acc[i][j][0], acc[i][j][1]);
            *(float2*)(Y + (size_t)(ra + 8) * HH + col) = make_float2(acc[i][j][2], acc[i][j][3]);
        }
    }
}

// ---------------- fused gather + epilogue ----------------
#define ACC4(A, V) { (A).x += (V).x; (A).y += (V).y; (A).z += (V).z; (A).w += (V).w; }

__global__ void k_gather_router(const float* __restrict__ rf, const float* __restrict__ br,
                                float* __restrict__ out) {
    int w = (blockIdx.x * blockDim.x + threadIdx.x) >> 5;
    int lane = threadIdx.x & 31;
    if (w >= NN) return;
    const float4* A = (const float4*)g_h[0];
    const float4* B = (const float4*)g_h[1];
    float4 acc = {0.f, 0.f, 0.f, 0.f};
    int s = g_rowptr[0][w], e = g_rowptr[0][w + 1];
    int k = s;
    for (; k + 1 < e; k += 2) {
        float4 v0 = __ldg(A + (size_t)g_col[0][k] * 32 + lane);
        float4 v1 = __ldg(A + (size_t)g_col[0][k + 1] * 32 + lane);
        ACC4(acc, v0); ACC4(acc, v1);
    }
    if (k < e) { float4 v = __ldg(A + (size_t)g_col[0][k] * 32 + lane); ACC4(acc, v); }

    s = g_rowptr[1][w]; e = g_rowptr[1][w + 1];
    k = s;
    for (; k + 1 < e; k += 2) {
        float4 v0 = __ldg(B + (size_t)g_col[1][k] * 32 + lane);
        float4 v1 = __ldg(B + (size_t)g_col[1][k + 1] * 32 + lane);
        ACC4(acc, v0); ACC4(acc, v1);
    }
    if (k < e) { float4 v = __ldg(B + (size_t)g_col[1][k] * 32 + lane); ACC4(acc, v); }

    float4 bv = __ldg((const float4*)br + lane);
    float4 rv = __ldg((const float4*)rf + (size_t)w * 32 + lane);
    float4 o;
    o.x = rv.x + fmaxf(acc.x + bv.x, 0.f);
    o.y = rv.y + fmaxf(acc.y + bv.y, 0.f);
    o.z = rv.z + fmaxf(acc.z + bv.z, 0.f);
    o.w = rv.w + fmaxf(acc.w + bv.w, 0.f);
    ((float4*)out)[(size_t)w * 32 + lane] = o;
}

__global__ void k_gather_packet(const float* __restrict__ pf, const float* __restrict__ bp,
                                float* __restrict__ out) {
    int w = (blockIdx.x * blockDim.x + threadIdx.x) >> 5;
    int lane = threadIdx.x & 31;
    if (w >= NN) return;
    const float4* C = (const float4*)g_h[2];
    float4 acc = {0.f, 0.f, 0.f, 0.f};
    int s = g_rowptr[2][w], e = g_rowptr[2][w + 1];
    int k = s;
    for (; k + 1 < e; k += 2) {
        float4 v0 = __ldg(C + (size_t)g_col[2][k] * 32 + lane);
        float4 v1 = __ldg(C + (size_t)g_col[2][k + 1] * 32 + lane);
        ACC4(acc, v0); ACC4(acc, v1);
    }
    if (k < e) { float4 v = __ldg(C + (size_t)g_col[2][k] * 32 + lane); ACC4(acc, v); }

    float scl = 1.0f / (float)max(e - s, 1);
    float4 bv = __ldg((const float4*)bp + lane);
    float4 rv = __ldg((const float4*)pf + (size_t)w * 32 + lane);
    float4 o;
    o.x = rv.x + fmaxf(acc.x * scl + bv.x, 0.f);
    o.y = rv.y + fmaxf(acc.y * scl + bv.y, 0.f);
    o.z = rv.z + fmaxf(acc.z * scl + bv.z, 0.f);
    o.w = rv.w + fmaxf(acc.w * scl + bv.w, 0.f);
    ((float4*)out)[(size_t)w * 32 + lane] = o;
}

// ---------------- launch: fork-join overlap of CSR build and GEMMs ----------------
extern "C" void kernel_launch(void* const* d_in, const int* in_sizes, int n_in,
                              void* d_out, int out_size) {
    const float* router_feat  = (const float*)d_in[0];
    const float* packet_feat  = (const float*)d_in[1];
    const float* W_r          = (const float*)d_in[2];
    const float* b_r          = (const float*)d_in[3];
    const float* W_p          = (const float*)d_in[4];
    const float* b_p          = (const float*)d_in[5];
    const int*   pass_src     = (const int*)d_in[6];
    const int*   pass_dst     = (const int*)d_in[7];
    const int*   transfer_src = (const int*)d_in[8];
    const int*   transfer_dst = (const int*)d_in[9];
    const int*   connect_src  = (const int*)d_in[10];
    const int*   connect_dst  = (const int*)d_in[11];
    float* out = (float*)d_out;

    static cudaStream_t s1 = nullptr;
    static cudaEvent_t evFork, evG, evF, evP;
    if (!s1) {
        cudaStreamCreateWithFlags(&s1, cudaStreamNonBlocking);
        cudaEventCreateWithFlags(&evFork, cudaEventDisableTiming);
        cudaEventCreateWithFlags(&evG, cudaEventDisableTiming);
        cudaEventCreateWithFlags(&evF, cudaEventDisableTiming);
        cudaEventCreateWithFlags(&evP, cudaEventDisableTiming);
        const int smem_bytes = 2 * 128 * XS * 4;
        cudaFuncSetAttribute(k_gemm_plain<256>, cudaFuncAttributeMaxDynamicSharedMemorySize, smem_bytes);
        cudaFuncSetAttribute(k_gemm_plain<128>, cudaFuncAttributeMaxDynamicSharedMemorySize, smem_bytes);
    }
    const int smem_bytes = 2 * 128 * XS * 4;

    float* hbase;   cudaGetSymbolAddress((void**)&hbase, g_h);
    int*   degbase; cudaGetSymbolAddress((void**)&degbase, g_deg);
    float* hA = hbase;
    float* hB = hbase + (size_t)NN * HH;
    float* hC = hbase + 2 * (size_t)NN * HH;

    // fork s1 off the capture (null) stream
    cudaEventRecord(evFork, 0);
    cudaStreamWaitEvent(s1, evFork, 0);

    // s1: the three dense GEMMs (independent of the graph structure)
    k_gemm_plain<256><<<NN / 128, 256, smem_bytes, s1>>>(packet_feat, W_r,       hA);
    k_gemm_plain<256><<<NN / 128, 256, smem_bytes, s1>>>(router_feat, W_r + 128, hB);
    k_gemm_plain<128><<<NN / 128, 256, smem_bytes, s1>>>(router_feat, W_p,       hC);
    cudaEventRecord(evG, s1);

    // s0 (null): CSR build
    cudaMemsetAsync(degbase, 0, 3 * NN * sizeof(int), 0);
    k_hist<<<(3 * EE + 255) / 256, 256>>>(pass_dst, connect_dst, transfer_dst);
    k_scan<<<3, 1024>>>();
    k_fill<<<(3 * EE + 255) / 256, 256>>>(pass_src, pass_dst, connect_src, connect_dst,
                                          transfer_src, transfer_dst);
    cudaEventRecord(evF, 0);

    // gathers: router on s0 (waits for GEMMs), packet on s1 (waits for CSR)
    cudaStreamWaitEvent(0, evG, 0);
    k_gather_router<<<NN / 8, 256>>>(router_feat, b_r, out);
    cudaStreamWaitEvent(s1, evF, 0);
    k_gather_packet<<<NN / 8, 256, 0, s1>>>(packet_feat, b_p, out + (size_t)NN * HH);

    // join back to capture stream
    cudaEventRecord(evP, s1);
    cudaStreamWaitEvent(0, evP, 0);
}

// round 4
// speedup vs baseline: 1.0919x; 1.0919x over previous
#include <cuda_runtime.h>
#include <cuda_fp16.h>
#include <cstdint>

#define NN 65536
#define HH 128
#define EE 524288

// ---------------- static scratch ----------------
__device__ int    g_deg[3][NN];
__device__ int    g_rowptr[3][NN + 1];
__device__ int    g_cursor[3][NN];
__device__ int    g_col[3][EE];
__device__ float  g_h[3][NN * HH];      // 0: h1_r (pass), 1: h2_r (connect), 2: transfer sum
__device__ __half g_rf16[NN * HH];
__device__ __half g_pf16[NN * HH];

// ---------------- fp16 conversion of feature tables ----------------
__global__ void k_f16(const float* __restrict__ rf, const float* __restrict__ pf) {
    int i = blockIdx.x * blockDim.x + threadIdx.x;   // 8 floats per thread
    const int half_total = NN * HH / 8;
    const float4* src;
    __half* dst;
    int base;
    if (i < half_total) { src = (const float4*)rf; dst = g_rf16; base = i; }
    else                { src = (const float4*)pf; dst = g_pf16; base = i - half_total; }
    float4 v0 = __ldg(src + base * 2);
    float4 v1 = __ldg(src + base * 2 + 1);
    __half2 h[4];
    h[0] = __floats2half2_rn(v0.x, v0.y);
    h[1] = __floats2half2_rn(v0.z, v0.w);
    h[2] = __floats2half2_rn(v1.x, v1.y);
    h[3] = __floats2half2_rn(v1.z, v1.w);
    *(uint4*)(dst + (size_t)base * 8) = *(uint4*)h;
}

// ---------------- CSR build ----------------
__global__ void k_hist(const int* __restrict__ pass_dst,
                       const int* __restrict__ connect_dst,
                       const int* __restrict__ transfer_dst) {
    int i = blockIdx.x * blockDim.x + threadIdx.x;
    if (i >= 3 * EE) return;
    int r = i / EE, e = i - r * EE;
    const int* dst = (r == 0) ? pass_dst : (r == 1) ? connect_dst : transfer_dst;
    atomicAdd(&g_deg[r][dst[e]], 1);
}

__global__ void k_scan() {
    const int CH = NN / 1024;
    int r = blockIdx.x;
    int t = threadIdx.x;
    int base = t * CH;
    int s = 0;
    for (int j = 0; j < CH; j++) s += g_deg[r][base + j];

    __shared__ int sm[1024];
    sm[t] = s;
    __syncthreads();
    for (int off = 1; off < 1024; off <<= 1) {
        int v = (t >= off) ? sm[t - off] : 0;
        __syncthreads();
        sm[t] += v;
        __syncthreads();
    }
    int run = sm[t] - s;
    for (int j = 0; j < CH; j++) {
        g_rowptr[r][base + j] = run;
        g_cursor[r][base + j] = run;
        run += g_deg[r][base + j];
    }
    if (t == 1023) g_rowptr[r][NN] = run;
}

__global__ void k_fill(const int* __restrict__ pass_src, const int* __restrict__ pass_dst,
                       const int* __restrict__ connect_src, const int* __restrict__ connect_dst,
                       const int* __restrict__ transfer_src, const int* __restrict__ transfer_dst) {
    int i = blockIdx.x * blockDim.x + threadIdx.x;
    if (i >= 3 * EE) return;
    int r = i / EE, e = i - r * EE;
    const int *src, *dst;
    if (r == 0)      { src = pass_src;     dst = pass_dst; }
    else if (r == 1) { src = connect_src;  dst = connect_dst; }
    else             { src = transfer_src; dst = transfer_dst; }
    int d = dst[e];
    int pos = atomicAdd(&g_cursor[r][d], 1);
    g_col[r][pos] = src[e];
}

// ---------------- gather from fp16 tables (half-warp per node) ----------------
__global__ void k_gather16() {
    int gtid = blockIdx.x * blockDim.x + threadIdx.x;
    int hw = gtid >> 4;          // half-warp id
    int ln = gtid & 15;          // lane within half-warp: 8 halves each
    if (hw >= 3 * NN) return;
    int r = hw >> 16;            // hw / NN
    int i = hw & (NN - 1);
    const uint4* tab = (const uint4*)((r == 0) ? g_pf16 : g_rf16);  // 16 uint4 per row

    int s = g_rowptr[r][i], e = g_rowptr[r][i + 1];
    float2 a0 = {0,0}, a1 = {0,0}, a2 = {0,0}, a3 = {0,0};
    int k = s;
    for (; k + 1 < e; k += 2) {
        int c0 = g_col[r][k], c1 = g_col[r][k + 1];
        uint4 v0 = __ldg(tab + (size_t)c0 * 16 + ln);
        uint4 v1 = __ldg(tab + (size_t)c1 * 16 + ln);
        const __half2* p0 = (const __half2*)&v0;
        const __half2* p1 = (const __half2*)&v1;
        float2 f;
        f = __half22float2(p0[0]); a0.x += f.x; a0.y += f.y;
        f = __half22float2(p0[1]); a1.x += f.x; a1.y += f.y;
        f = __half22float2(p0[2]); a2.x += f.x; a2.y += f.y;
        f = __half22float2(p0[3]); a3.x += f.x; a3.y += f.y;
        f = __half22float2(p1[0]); a0.x += f.x; a0.y += f.y;
        f = __half22float2(p1[1]); a1.x += f.x; a1.y += f.y;
        f = __half22float2(p1[2]); a2.x += f.x; a2.y += f.y;
        f = __half22float2(p1[3]); a3.x += f.x; a3.y += f.y;
    }
    if (k < e) {
        int c0 = g_col[r][k];
        uint4 v0 = __ldg(tab + (size_t)c0 * 16 + ln);
        const __half2* p0 = (const __half2*)&v0;
        float2 f;
        f = __half22float2(p0[0]); a0.x += f.x; a0.y += f.y;
        f = __half22float2(p0[1]); a1.x += f.x; a1.y += f.y;
        f = __half22float2(p0[2]); a2.x += f.x; a2.y += f.y;
        f = __half22float2(p0[3]); a3.x += f.x; a3.y += f.y;
    }
    float4* dst = (float4*)(g_h[r] + (size_t)i * HH) + ln * 2;
    dst[0] = make_float4(a0.x, a0.y, a1.x, a1.y);
    dst[1] = make_float4(a2.x, a2.y, a3.x, a3.y);
}

// ---------------- tf32 tensor-core fused linear + ReLU + residual ----------------
__device__ __forceinline__ uint32_t f2tf32(float x) {
    uint32_t r;
    asm("cvt.rna.tf32.f32 %0, %1;" : "=r"(r) : "f"(x));
    return r;
}

__device__ __forceinline__ void mma_tf32(float* d, const uint32_t* a, const uint32_t* b) {
    asm volatile(
        "mma.sync.aligned.m16n8k8.row.col.f32.tf32.tf32.f32 "
        "{%0,%1,%2,%3},{%4,%5,%6,%7},{%8,%9},{%0,%1,%2,%3};"
        : "+f"(d[0]), "+f"(d[1]), "+f"(d[2]), "+f"(d[3])
        : "r"(a[0]), "r"(a[1]), "r"(a[2]), "r"(a[3]), "r"(b[0]), "r"(b[1]));
}

#define KC 64
#define XS 68   // padded smem stride (4B words)

// out[row,n] = res[row,n] + relu( sum_k X[row,k]*W[n,k] * (mean scale if !ROUTER) + bias[n] )
template<int KTOT, bool ROUTER>
__global__ void __launch_bounds__(256, 2) k_gemm_tc(const float* __restrict__ res,
                                                    const float* __restrict__ W,
                                                    const float* __restrict__ bias,
                                                    float* __restrict__ out) {
    extern __shared__ uint32_t smemU[];
    uint32_t* sX = smemU;                 // [128][XS] tf32 bits
    uint32_t* sW = smemU + 128 * XS;

    const int t = threadIdx.x;
    const int warp = t >> 5, lane = t & 31;
    const int g = lane >> 2, tg = lane & 3;
    const int mw = (warp & 3) * 32;
    const int nw = (warp >> 2) * 64;
    const int row0 = blockIdx.x * 128;

    float acc[2][8][4];
    #pragma unroll
    for (int i = 0; i < 2; i++)
        #pragma unroll
        for (int j = 0; j < 8; j++)
            #pragma unroll
            for (int q = 0; q < 4; q++) acc[i][j][q] = 0.f;

    #pragma unroll
    for (int c = 0; c < KTOT / KC; c++) {
        const float* xsrc;
        int koff;
        if (ROUTER) { xsrc = (c < 2) ? g_h[0] : g_h[1]; koff = (c & 1) * KC; }
        else        { xsrc = g_h[2];                    koff = c * KC; }

        __syncthreads();
        #pragma unroll
        for (int it = 0; it < 8; it++) {
            int idx = it * 256 + t;          // 2048 float4 per buffer
            int row = idx >> 4, c4 = idx & 15;
            float4 xv = __ldg((const float4*)(xsrc + (size_t)(row0 + row) * HH + koff) + c4);
            uint32_t* dx = &sX[row * XS + c4 * 4];
            dx[0] = f2tf32(xv.x); dx[1] = f2tf32(xv.y); dx[2] = f2tf32(xv.z); dx[3] = f2tf32(xv.w);
            float4 wv = __ldg((const float4*)(W + (size_t)row * KTOT + c * KC) + c4);
            uint32_t* dw = &sW[row * XS + c4 * 4];
            dw[0] = f2tf32(wv.x); dw[1] = f2tf32(wv.y); dw[2] = f2tf32(wv.z); dw[3] = f2tf32(wv.w);
        }
        __syncthreads();

        #pragma unroll
        for (int ks = 0; ks < KC / 8; ks++) {
            int k0 = ks * 8;
            uint32_t a[2][4], b[8][2];
            #pragma unroll
            for (int i = 0; i < 2; i++) {
                int r = mw + i * 16 + g;
                a[i][0] = sX[r * XS + k0 + tg];
                a[i][1] = sX[(r + 8) * XS + k0 + tg];
                a[i][2] = sX[r * XS + k0 + tg + 4];
                a[i][3] = sX[(r + 8) * XS + k0 + tg + 4];
            }
            #pragma unroll
            for (int j = 0; j < 8; j++) {
                int n = nw + j * 8 + g;
                b[j][0] = sW[n * XS + k0 + tg];
                b[j][1] = sW[n * XS + k0 + tg + 4];
            }
            #pragma unroll
            for (int i = 0; i < 2; i++)
                #pragma unroll
                for (int j = 0; j < 8; j++)
                    mma_tf32(acc[i][j], a[i], b[j]);
        }
    }

    // ---- epilogue: (mean) + bias + relu + residual ----
    float scl[2][2];
    #pragma unroll
    for (int i = 0; i < 2; i++) {
        if (ROUTER) { scl[i][0] = 1.f; scl[i][1] = 1.f; }
        else {
            int ra = row0 + mw + i * 16 + g;
            int d0 = g_rowptr[2][ra + 1] - g_rowptr[2][ra];
            int d1 = g_rowptr[2][ra + 9] - g_rowptr[2][ra + 8];
            scl[i][0] = 1.f / (float)max(d0, 1);
            scl[i][1] = 1.f / (float)max(d1, 1);
        }
    }

    #pragma unroll
    for (int j = 0; j < 8; j++) {
        int col = nw + j * 8 + 2 * tg;
        float2 bv = *(const float2*)(bias + col);
        #pragma unroll
        for (int i = 0; i < 2; i++) {
            int ra = row0 + mw + i * 16 + g;
            float2 r0v = __ldg((const float2*)(res + (size_t)ra * HH + col));
            float2 r1v = __ldg((const float2*)(res + (size_t)(ra + 8) * HH + col));
            float2 o0, o1;
            o0.x = r0v.x + fmaxf(acc[i][j][0] * scl[i][0] + bv.x, 0.f);
            o0.y = r0v.y + fmaxf(acc[i][j][1] * scl[i][0] + bv.y, 0.f);
            o1.x = r1v.x + fmaxf(acc[i][j][2] * scl[i][1] + bv.x, 0.f);
            o1.y = r1v.y + fmaxf(acc[i][j][3] * scl[i][1] + bv.y, 0.f);
            *(float2*)(out + (size_t)ra * HH + col) = o0;
            *(float2*)(out + (size_t)(ra + 8) * HH + col) = o1;
        }
    }
}

// ---------------- launch (single stream) ----------------
extern "C" void kernel_launch(void* const* d_in, const int* in_sizes, int n_in,
                              void* d_out, int out_size) {
    const float* router_feat  = (const float*)d_in[0];
    const float* packet_feat  = (const float*)d_in[1];
    const float* W_r          = (const float*)d_in[2];
    const float* b_r          = (const float*)d_in[3];
    const float* W_p          = (const float*)d_in[4];
    const float* b_p          = (const float*)d_in[5];
    const int*   pass_src     = (const int*)d_in[6];
    const int*   pass_dst     = (const int*)d_in[7];
    const int*   transfer_src = (const int*)d_in[8];
    const int*   transfer_dst = (const int*)d_in[9];
    const int*   connect_src  = (const int*)d_in[10];
    const int*   connect_dst  = (const int*)d_in[11];
    float* out = (float*)d_out;

    const int smem_bytes = 2 * 128 * XS * 4;   // 69,632 B
    cudaFuncSetAttribute(k_gemm_tc<256, true>,  cudaFuncAttributeMaxDynamicSharedMemorySize, smem_bytes);
    cudaFuncSetAttribute(k_gemm_tc<128, false>, cudaFuncAttributeMaxDynamicSharedMemorySize, smem_bytes);

    int* degbase;
    cudaGetSymbolAddress((void**)&degbase, g_deg);
    cudaMemsetAsync(degbase, 0, 3 * NN * sizeof(int), 0);

    k_f16<<<2 * NN * HH / 8 / 256, 256>>>(router_feat, packet_feat);
    k_hist<<<(3 * EE + 255) / 256, 256>>>(pass_dst, connect_dst, transfer_dst);
    k_scan<<<3, 1024>>>();
    k_fill<<<(3 * EE + 255) / 256, 256>>>(pass_src, pass_dst, connect_src, connect_dst,
                                          transfer_src, transfer_dst);
    k_gather16<<<3 * NN * 16 / 256, 256>>>();
    k_gemm_tc<256, true ><<<NN / 128, 256, smem_bytes>>>(router_feat, W_r, b_r, out);
    k_gemm_tc<128, false><<<NN / 128, 256, smem_bytes>>>(packet_feat, W_p, b_p, out + (size_t)NN * HH);
}

// round 5
// speedup vs baseline: 1.2040x; 1.1026x over previous
#include <cuda_runtime.h>
#include <cuda_fp16.h>
#include <cstdint>

#define NN 65536
#define HH 128
#define EE 524288

// ---------------- static scratch ----------------
__device__ int    g_deg[3][NN];
__device__ int    g_rowptr[3][NN + 1];
__device__ int    g_cursor[3][NN];
__device__ int    g_col[3][EE];
__device__ __half g_h16[3][NN * HH];    // fp16 aggregation results
__device__ __half g_rf16[NN * HH];
__device__ __half g_pf16[NN * HH];
__device__ __half g_wr16[HH * 256];
__device__ __half g_wp16[HH * HH];

// ---------------- fp16 conversion: feature tables ----------------
__global__ void k_f16(const float* __restrict__ rf, const float* __restrict__ pf) {
    int i = blockIdx.x * blockDim.x + threadIdx.x;   // 8 floats per thread
    const int half_total = NN * HH / 8;
    const float4* src;
    __half* dst;
    int base;
    if (i < half_total) { src = (const float4*)rf; dst = g_rf16; base = i; }
    else                { src = (const float4*)pf; dst = g_pf16; base = i - half_total; }
    float4 v0 = __ldg(src + base * 2);
    float4 v1 = __ldg(src + base * 2 + 1);
    __half2 h[4];
    h[0] = __floats2half2_rn(v0.x, v0.y);
    h[1] = __floats2half2_rn(v0.z, v0.w);
    h[2] = __floats2half2_rn(v1.x, v1.y);
    h[3] = __floats2half2_rn(v1.z, v1.w);
    *(uint4*)(dst + (size_t)base * 8) = *(uint4*)h;
}

// ---------------- fp16 conversion: weights ----------------
__global__ void k_w16(const float* __restrict__ Wr, const float* __restrict__ Wp) {
    int i = blockIdx.x * blockDim.x + threadIdx.x;   // one half2 per thread
    if (i < 16384) {
        float2 v = __ldg((const float2*)Wr + i);
        *(__half2*)(g_wr16 + i * 2) = __floats2half2_rn(v.x, v.y);
    } else if (i < 24576) {
        int j = i - 16384;
        float2 v = __ldg((const float2*)Wp + j);
        *(__half2*)(g_wp16 + j * 2) = __floats2half2_rn(v.x, v.y);
    }
}

// ---------------- CSR build ----------------
__global__ void k_hist(const int* __restrict__ pass_dst,
                       const int* __restrict__ connect_dst,
                       const int* __restrict__ transfer_dst) {
    int i = blockIdx.x * blockDim.x + threadIdx.x;
    if (i >= 3 * EE) return;
    int r = i / EE, e = i - r * EE;
    const int* dst = (r == 0) ? pass_dst : (r == 1) ? connect_dst : transfer_dst;
    atomicAdd(&g_deg[r][dst[e]], 1);
}

__global__ void k_scan() {
    const int CH = NN / 1024;
    int r = blockIdx.x;
    int t = threadIdx.x;
    int base = t * CH;
    int s = 0;
    for (int j = 0; j < CH; j++) s += g_deg[r][base + j];

    __shared__ int sm[1024];
    sm[t] = s;
    __syncthreads();
    for (int off = 1; off < 1024; off <<= 1) {
        int v = (t >= off) ? sm[t - off] : 0;
        __syncthreads();
        sm[t] += v;
        __syncthreads();
    }
    int run = sm[t] - s;
    for (int j = 0; j < CH; j++) {
        g_rowptr[r][base + j] = run;
        g_cursor[r][base + j] = run;
        run += g_deg[r][base + j];
    }
    if (t == 1023) g_rowptr[r][NN] = run;
}

__global__ void k_fill(const int* __restrict__ pass_src, const int* __restrict__ pass_dst,
                       const int* __restrict__ connect_src, const int* __restrict__ connect_dst,
                       const int* __restrict__ transfer_src, const int* __restrict__ transfer_dst) {
    int i = blockIdx.x * blockDim.x + threadIdx.x;
    if (i >= 3 * EE) return;
    int r = i / EE, e = i - r * EE;
    const int *src, *dst;
    if (r == 0)      { src = pass_src;     dst = pass_dst; }
    else if (r == 1) { src = connect_src;  dst = connect_dst; }
    else             { src = transfer_src; dst = transfer_dst; }
    int d = dst[e];
    int pos = atomicAdd(&g_cursor[r][d], 1);
    g_col[r][pos] = src[e];
}

// ---------------- gather (fp32 accumulate, fp16 store) ----------------
__global__ void k_gather16() {
    int gtid = blockIdx.x * blockDim.x + threadIdx.x;
    int hw = gtid >> 4;          // half-warp id
    int ln = gtid & 15;          // lane: 8 halves each
    if (hw >= 3 * NN) return;
    int r = hw >> 16;
    int i = hw & (NN - 1);
    const uint4* tab = (const uint4*)((r == 0) ? g_pf16 : g_rf16);  // 16 uint4 per row

    int s = g_rowptr[r][i], e = g_rowptr[r][i + 1];
    float2 a0 = {0,0}, a1 = {0,0}, a2 = {0,0}, a3 = {0,0};
    int k = s;
    for (; k + 1 < e; k += 2) {
        int c0 = g_col[r][k], c1 = g_col[r][k + 1];
        uint4 v0 = __ldg(tab + (size_t)c0 * 16 + ln);
        uint4 v1 = __ldg(tab + (size_t)c1 * 16 + ln);
        const __half2* p0 = (const __half2*)&v0;
        const __half2* p1 = (const __half2*)&v1;
        float2 f;
        f = __half22float2(p0[0]); a0.x += f.x; a0.y += f.y;
        f = __half22float2(p0[1]); a1.x += f.x; a1.y += f.y;
        f = __half22float2(p0[2]); a2.x += f.x; a2.y += f.y;
        f = __half22float2(p0[3]); a3.x += f.x; a3.y += f.y;
        f = __half22float2(p1[0]); a0.x += f.x; a0.y += f.y;
        f = __half22float2(p1[1]); a1.x += f.x; a1.y += f.y;
        f = __half22float2(p1[2]); a2.x += f.x; a2.y += f.y;
        f = __half22float2(p1[3]); a3.x += f.x; a3.y += f.y;
    }
    if (k < e) {
        int c0 = g_col[r][k];
        uint4 v0 = __ldg(tab + (size_t)c0 * 16 + ln);
        const __half2* p0 = (const __half2*)&v0;
        float2 f;
        f = __half22float2(p0[0]); a0.x += f.x; a0.y += f.y;
        f = __half22float2(p0[1]); a1.x += f.x; a1.y += f.y;
        f = __half22float2(p0[2]); a2.x += f.x; a2.y += f.y;
        f = __half22float2(p0[3]); a3.x += f.x; a3.y += f.y;
    }
    __half2 h[4];
    h[0] = __floats2half2_rn(a0.x, a0.y);
    h[1] = __floats2half2_rn(a1.x, a1.y);
    h[2] = __floats2half2_rn(a2.x, a2.y);
    h[3] = __floats2half2_rn(a3.x, a3.y);
    *((uint4*)(g_h16[r] + (size_t)i * HH) + ln) = *(uint4*)h;
}

// ---------------- fp16 tensor-core fused linear + ReLU + residual ----------------
__device__ __forceinline__ void mma_f16(float* d, const uint32_t* a, const uint32_t* b) {
    asm volatile(
        "mma.sync.aligned.m16n8k16.row.col.f32.f16.f16.f32 "
        "{%0,%1,%2,%3},{%4,%5,%6,%7},{%8,%9},{%0,%1,%2,%3};"
        : "+f"(d[0]), "+f"(d[1]), "+f"(d[2]), "+f"(d[3])
        : "r"(a[0]), "r"(a[1]), "r"(a[2]), "r"(a[3]), "r"(b[0]), "r"(b[1]));
}

#define KC 64
#define XSH 72   // padded smem stride in halves (144B rows; 16B-aligned; banks 4g+tg conflict-free)

// out[row,n] = res[row,n] + relu( sum_k X[row,k]*W[n,k] * (mean if !ROUTER) + bias[n] )
template<int KTOT, bool ROUTER>
__global__ void __launch_bounds__(256, 2) k_gemm_f16(const float* __restrict__ res,
                                                     const float* __restrict__ bias,
                                                     float* __restrict__ out) {
    __shared__ __half sX[128 * XSH];
    __shared__ __half sW[128 * XSH];

    const int t = threadIdx.x;
    const int warp = t >> 5, lane = t & 31;
    const int g = lane >> 2, tg = lane & 3;
    const int mw = (warp & 3) * 32;
    const int nw = (warp >> 2) * 64;
    const int row0 = blockIdx.x * 128;
    const __half* Wh = ROUTER ? g_wr16 : g_wp16;

    float acc[2][8][4];
    #pragma unroll
    for (int i = 0; i < 2; i++)
        #pragma unroll
        for (int j = 0; j < 8; j++)
            #pragma unroll
            for (int q = 0; q < 4; q++) acc[i][j][q] = 0.f;

    #pragma unroll
    for (int c = 0; c < KTOT / KC; c++) {
        const __half* xsrc;
        int koff;
        if (ROUTER) { xsrc = (c < 2) ? g_h16[0] : g_h16[1]; koff = (c & 1) * KC; }
        else        { xsrc = g_h16[2];                       koff = c * KC; }

        __syncthreads();
        #pragma unroll
        for (int it = 0; it < 4; it++) {
            int idx = it * 256 + t;           // 1024 uint4 per buffer
            int row = idx >> 3, c8 = idx & 7; // 8 uint4 (64 halves) per row
            uint4 xv = __ldg((const uint4*)(xsrc + (size_t)(row0 + row) * HH + koff) + c8);
            *(uint4*)&sX[row * XSH + c8 * 8] = xv;
            uint4 wv = __ldg((const uint4*)(Wh + (size_t)row * KTOT + c * KC) + c8);
            *(uint4*)&sW[row * XSH + c8 * 8] = wv;
        }
        __syncthreads();

        #pragma unroll
        for (int ks = 0; ks < KC / 16; ks++) {
            int k0 = ks * 16;
            uint32_t a[2][4], b[8][2];
            #pragma unroll
            for (int i = 0; i < 2; i++) {
                int r = mw + i * 16 + g;
                a[i][0] = *(const uint32_t*)&sX[r * XSH + k0 + 2 * tg];
                a[i][1] = *(const uint32_t*)&sX[(r + 8) * XSH + k0 + 2 * tg];
                a[i][2] = *(const uint32_t*)&sX[r * XSH + k0 + 8 + 2 * tg];
                a[i][3] = *(const uint32_t*)&sX[(r + 8) * XSH + k0 + 8 + 2 * tg];
            }
            #pragma unroll
            for (int j = 0; j < 8; j++) {
                int n = nw + j * 8 + g;
                b[j][0] = *(const uint32_t*)&sW[n * XSH + k0 + 2 * tg];
                b[j][1] = *(const uint32_t*)&sW[n * XSH + k0 + 8 + 2 * tg];
            }
            #pragma unroll
            for (int i = 0; i < 2; i++)
                #pragma unroll
                for (int j = 0; j < 8; j++)
                    mma_f16(acc[i][j], a[i], b[j]);
        }
    }

    // ---- epilogue: (mean) + bias + relu + residual ----
    float scl[2][2];
    #pragma unroll
    for (int i = 0; i < 2; i++) {
        if (ROUTER) { scl[i][0] = 1.f; scl[i][1] = 1.f; }
        else {
            int ra = row0 + mw + i * 16 + g;
            int d0 = g_rowptr[2][ra + 1] - g_rowptr[2][ra];
            int d1 = g_rowptr[2][ra + 9] - g_rowptr[2][ra + 8];
            scl[i][0] = 1.f / (float)max(d0, 1);
            scl[i][1] = 1.f / (float)max(d1, 1);
        }
    }

    #pragma unroll
    for (int j = 0; j < 8; j++) {
        int col = nw + j * 8 + 2 * tg;
        float2 bv = *(const float2*)(bias + col);
        #pragma unroll
        for (int i = 0; i < 2; i++) {
            int ra = row0 + mw + i * 16 + g;
            float2 r0v = __ldg((const float2*)(res + (size_t)ra * HH + col));
            float2 r1v = __ldg((const float2*)(res + (size_t)(ra + 8) * HH + col));
            float2 o0, o1;
            o0.x = r0v.x + fmaxf(acc[i][j][0] * scl[i][0] + bv.x, 0.f);
            o0.y = r0v.y + fmaxf(acc[i][j][1] * scl[i][0] + bv.y, 0.f);
            o1.x = r1v.x + fmaxf(acc[i][j][2] * scl[i][1] + bv.x, 0.f);
            o1.y = r1v.y + fmaxf(acc[i][j][3] * scl[i][1] + bv.y, 0.f);
            *(float2*)(out + (size_t)ra * HH + col) = o0;
            *(float2*)(out + (size_t)(ra + 8) * HH + col) = o1;
        }
    }
}

// ---------------- launch (single stream) ----------------
extern "C" void kernel_launch(void* const* d_in, const int* in_sizes, int n_in,
                              void* d_out, int out_size) {
    const float* router_feat  = (const float*)d_in[0];
    const float* packet_feat  = (const float*)d_in[1];
    const float* W_r          = (const float*)d_in[2];
    const float* b_r          = (const float*)d_in[3];
    const float* W_p          = (const float*)d_in[4];
    const float* b_p          = (const float*)d_in[5];
    const int*   pass_src     = (const int*)d_in[6];
    const int*   pass_dst     = (const int*)d_in[7];
    const int*   transfer_src = (const int*)d_in[8];
    const int*   transfer_dst = (const int*)d_in[9];
    const int*   connect_src  = (const int*)d_in[10];
    const int*   connect_dst  = (const int*)d_in[11];
    float* out = (float*)d_out;

    int* degbase;
    cudaGetSymbolAddress((void**)&degbase, g_deg);
    cudaMemsetAsync(degbase, 0, 3 * NN * sizeof(int), 0);

    k_f16<<<2 * NN * HH / 8 / 256, 256>>>(router_feat, packet_feat);
    k_w16<<<96, 256>>>(W_r, W_p);
    k_hist<<<(3 * EE + 255) / 256, 256>>>(pass_dst, connect_dst, transfer_dst);
    k_scan<<<3, 1024>>>();
    k_fill<<<(3 * EE + 255) / 256, 256>>>(pass_src, pass_dst, connect_src, connect_dst,
                                          transfer_src, transfer_dst);
    k_gather16<<<3 * NN * 16 / 256, 256>>>();
    k_gemm_f16<256, true ><<<NN / 128, 256>>>(router_feat, b_r, out);
    k_gemm_f16<128, false><<<NN / 128, 256>>>(packet_feat, b_p, out + (size_t)NN * HH);
}

// round 6
// speedup vs baseline: 2.4567x; 2.0406x over previous
#include <cuda_runtime.h>
#include <cuda_fp16.h>
#include <cstdint>

#define NN 65536
#define HH 128
#define EE 524288

// ---------------- static scratch ----------------
__device__ int    g_deg[3][NN];
__device__ int    g_rowptr[3][NN + 1];
__device__ int    g_cursor[3][NN];
__device__ int    g_csum[3][256];
__device__ int    g_col[3][EE];
__device__ __half g_h16[3][NN * HH];    // fp16 aggregation results
__device__ __half g_rf16[NN * HH];
__device__ __half g_pf16[NN * HH];
__device__ __half g_wr16[HH * 256];
__device__ __half g_wp16[HH * HH];

// ---------------- fp16 conversion: feature tables ----------------
__global__ void k_f16(const float* __restrict__ rf, const float* __restrict__ pf) {
    int i = blockIdx.x * blockDim.x + threadIdx.x;   // 8 floats per thread
    const int half_total = NN * HH / 8;
    const float4* src;
    __half* dst;
    int base;
    if (i < half_total) { src = (const float4*)rf; dst = g_rf16; base = i; }
    else                { src = (const float4*)pf; dst = g_pf16; base = i - half_total; }
    float4 v0 = __ldg(src + base * 2);
    float4 v1 = __ldg(src + base * 2 + 1);
    __half2 h[4];
    h[0] = __floats2half2_rn(v0.x, v0.y);
    h[1] = __floats2half2_rn(v0.z, v0.w);
    h[2] = __floats2half2_rn(v1.x, v1.y);
    h[3] = __floats2half2_rn(v1.z, v1.w);
    *(uint4*)(dst + (size_t)base * 8) = *(uint4*)h;
}

// ---------------- fp16 conversion: weights ----------------
__global__ void k_w16(const float* __restrict__ Wr, const float* __restrict__ Wp) {
    int i = blockIdx.x * blockDim.x + threadIdx.x;   // one half2 per thread
    if (i < 16384) {
        float2 v = __ldg((const float2*)Wr + i);
        *(__half2*)(g_wr16 + i * 2) = __floats2half2_rn(v.x, v.y);
    } else if (i < 24576) {
        int j = i - 16384;
        float2 v = __ldg((const float2*)Wp + j);
        *(__half2*)(g_wp16 + j * 2) = __floats2half2_rn(v.x, v.y);
    }
}

// ---------------- CSR build ----------------
__global__ void k_hist(const int* __restrict__ pass_dst,
                       const int* __restrict__ connect_dst,
                       const int* __restrict__ transfer_dst) {
    int i = blockIdx.x * blockDim.x + threadIdx.x;
    if (i >= 3 * EE) return;
    int r = i / EE, e = i - r * EE;
    const int* dst = (r == 0) ? pass_dst : (r == 1) ? connect_dst : transfer_dst;
    atomicAdd(&g_deg[r][dst[e]], 1);
}

// phase 1: block-local scan of 256-element chunks (768 blocks)
__global__ void k_scan1() {
    int b = blockIdx.x;              // 0..767
    int r = b >> 8, ch = b & 255;
    int t = threadIdx.x;
    int idx = ch * 256 + t;
    int v = g_deg[r][idx];
    __shared__ int sm[256];
    sm[t] = v;
    __syncthreads();
    #pragma unroll
    for (int off = 1; off < 256; off <<= 1) {
        int u = (t >= off) ? sm[t - off] : 0;
        __syncthreads();
        sm[t] += u;
        __syncthreads();
    }
    g_rowptr[r][idx] = sm[t] - v;    // chunk-local exclusive prefix
    if (t == 255) g_csum[r][ch] = sm[t];
}

// phase 2: scan the 256 chunk totals per relation (3 blocks)
__global__ void k_scan2() {
    int r = blockIdx.x;
    int t = threadIdx.x;
    int v = g_csum[r][t];
    __shared__ int sm[256];
    sm[t] = v;
    __syncthreads();
    #pragma unroll
    for (int off = 1; off < 256; off <<= 1) {
        int u = (t >= off) ? sm[t - off] : 0;
        __syncthreads();
        sm[t] += u;
        __syncthreads();
    }
    g_csum[r][t] = sm[t] - v;        // exclusive chunk offset
    if (t == 255) g_rowptr[r][NN] = sm[t];
}

// phase 3: add chunk offsets, mirror into cursor
__global__ void k_scan3() {
    int i = blockIdx.x * blockDim.x + threadIdx.x;
    if (i >= 3 * NN) return;
    int r = i >> 16, n = i & (NN - 1);
    int val = g_rowptr[r][n] + g_csum[r][n >> 8];
    g_rowptr[r][n] = val;
    g_cursor[r][n] = val;
}

__global__ void k_fill(const int* __restrict__ pass_src, const int* __restrict__ pass_dst,
                       const int* __restrict__ connect_src, const int* __restrict__ connect_dst,
                       const int* __restrict__ transfer_src, const int* __restrict__ transfer_dst) {
    int i = blockIdx.x * blockDim.x + threadIdx.x;
    if (i >= 3 * EE) return;
    int r = i / EE, e = i - r * EE;
    const int *src, *dst;
    if (r == 0)      { src = pass_src;     dst = pass_dst; }
    else if (r == 1) { src = connect_src;  dst = connect_dst; }
    else             { src = transfer_src; dst = transfer_dst; }
    int d = dst[e];
    int pos = atomicAdd(&g_cursor[r][d], 1);
    g_col[r][pos] = src[e];
}

// ---------------- gather (fp32 accumulate, fp16 store) ----------------
__global__ void k_gather16() {
    int gtid = blockIdx.x * blockDim.x + threadIdx.x;
    int hw = gtid >> 4;          // half-warp id
    int ln = gtid & 15;          // lane: 8 halves each
    if (hw >= 3 * NN) return;
    int r = hw >> 16;
    int i = hw & (NN - 1);
    const uint4* tab = (const uint4*)((r == 0) ? g_pf16 : g_rf16);  // 16 uint4 per row

    int s = g_rowptr[r][i], e = g_rowptr[r][i + 1];
    float2 a0 = {0,0}, a1 = {0,0}, a2 = {0,0}, a3 = {0,0};
    int k = s;
    for (; k + 1 < e; k += 2) {
        int c0 = g_col[r][k], c1 = g_col[r][k + 1];
        uint4 v0 = __ldg(tab + (size_t)c0 * 16 + ln);
        uint4 v1 = __ldg(tab + (size_t)c1 * 16 + ln);
        const __half2* p0 = (const __half2*)&v0;
        const __half2* p1 = (const __half2*)&v1;
        float2 f;
        f = __half22float2(p0[0]); a0.x += f.x; a0.y += f.y;
        f = __half22float2(p0[1]); a1.x += f.x; a1.y += f.y;
        f = __half22float2(p0[2]); a2.x += f.x; a2.y += f.y;
        f = __half22float2(p0[3]); a3.x += f.x; a3.y += f.y;
        f = __half22float2(p1[0]); a0.x += f.x; a0.y += f.y;
        f = __half22float2(p1[1]); a1.x += f.x; a1.y += f.y;
        f = __half22float2(p1[2]); a2.x += f.x; a2.y += f.y;
        f = __half22float2(p1[3]); a3.x += f.x; a3.y += f.y;
    }
    if (k < e) {
        int c0 = g_col[r][k];
        uint4 v0 = __ldg(tab + (size_t)c0 * 16 + ln);
        const __half2* p0 = (const __half2*)&v0;
        float2 f;
        f = __half22float2(p0[0]); a0.x += f.x; a0.y += f.y;
        f = __half22float2(p0[1]); a1.x += f.x; a1.y += f.y;
        f = __half22float2(p0[2]); a2.x += f.x; a2.y += f.y;
        f = __half22float2(p0[3]); a3.x += f.x; a3.y += f.y;
    }
    __half2 h[4];
    h[0] = __floats2half2_rn(a0.x, a0.y);
    h[1] = __floats2half2_rn(a1.x, a1.y);
    h[2] = __floats2half2_rn(a2.x, a2.y);
    h[3] = __floats2half2_rn(a3.x, a3.y);
    *((uint4*)(g_h16[r] + (size_t)i * HH) + ln) = *(uint4*)h;
}

// ---------------- fp16 tensor-core fused linear + ReLU + residual ----------------
__device__ __forceinline__ void mma_f16(float* d, const uint32_t* a, const uint32_t* b) {
    asm volatile(
        "mma.sync.aligned.m16n8k16.row.col.f32.f16.f16.f32 "
        "{%0,%1,%2,%3},{%4,%5,%6,%7},{%8,%9},{%0,%1,%2,%3};"
        : "+f"(d[0]), "+f"(d[1]), "+f"(d[2]), "+f"(d[3])
        : "r"(a[0]), "r"(a[1]), "r"(a[2]), "r"(a[3]), "r"(b[0]), "r"(b[1]));
}

#define KC 64
#define XSH 72   // padded smem stride in halves

template<int KTOT, bool ROUTER>
__global__ void __launch_bounds__(256, 2) k_gemm_f16(const float* __restrict__ res,
                                                     const float* __restrict__ bias,
                                                     float* __restrict__ out) {
    __shared__ __half sX[128 * XSH];
    __shared__ __half sW[128 * XSH];

    const int t = threadIdx.x;
    const int warp = t >> 5, lane = t & 31;
    const int g = lane >> 2, tg = lane & 3;
    const int mw = (warp & 3) * 32;
    const int nw = (warp >> 2) * 64;
    const int row0 = blockIdx.x * 128;
    const __half* Wh = ROUTER ? g_wr16 : g_wp16;

    float acc[2][8][4];
    #pragma unroll
    for (int i = 0; i < 2; i++)
        #pragma unroll
        for (int j = 0; j < 8; j++)
            #pragma unroll
            for (int q = 0; q < 4; q++) acc[i][j][q] = 0.f;

    #pragma unroll
    for (int c = 0; c < KTOT / KC; c++) {
        const __half* xsrc;
        int koff;
        if (ROUTER) { xsrc = (c < 2) ? g_h16[0] : g_h16[1]; koff = (c & 1) * KC; }
        else        { xsrc = g_h16[2];                       koff = c * KC; }

        __syncthreads();
        #pragma unroll
        for (int it = 0; it < 4; it++) {
            int idx = it * 256 + t;
            int row = idx >> 3, c8 = idx & 7;
            uint4 xv = __ldg((const uint4*)(xsrc + (size_t)(row0 + row) * HH + koff) + c8);
            *(uint4*)&sX[row * XSH + c8 * 8] = xv;
            uint4 wv = __ldg((const uint4*)(Wh + (size_t)row * KTOT + c * KC) + c8);
            *(uint4*)&sW[row * XSH + c8 * 8] = wv;
        }
        __syncthreads();

        #pragma unroll
        for (int ks = 0; ks < KC / 16; ks++) {
            int k0 = ks * 16;
            uint32_t a[2][4], b[8][2];
            #pragma unroll
            for (int i = 0; i < 2; i++) {
                int r = mw + i * 16 + g;
                a[i][0] = *(const uint32_t*)&sX[r * XSH + k0 + 2 * tg];
                a[i][1] = *(const uint32_t*)&sX[(r + 8) * XSH + k0 + 2 * tg];
                a[i][2] = *(const uint32_t*)&sX[r * XSH + k0 + 8 + 2 * tg];
                a[i][3] = *(const uint32_t*)&sX[(r + 8) * XSH + k0 + 8 + 2 * tg];
            }
            #pragma unroll
            for (int j = 0; j < 8; j++) {
                int n = nw + j * 8 + g;
                b[j][0] = *(const uint32_t*)&sW[n * XSH + k0 + 2 * tg];
                b[j][1] = *(const uint32_t*)&sW[n * XSH + k0 + 8 + 2 * tg];
            }
            #pragma unroll
            for (int i = 0; i < 2; i++)
                #pragma unroll
                for (int j = 0; j < 8; j++)
                    mma_f16(acc[i][j], a[i], b[j]);
        }
    }

    float scl[2][2];
    #pragma unroll
    for (int i = 0; i < 2; i++) {
        if (ROUTER) { scl[i][0] = 1.f; scl[i][1] = 1.f; }
        else {
            int ra = row0 + mw + i * 16 + g;
            int d0 = g_rowptr[2][ra + 1] - g_rowptr[2][ra];
            int d1 = g_rowptr[2][ra + 9] - g_rowptr[2][ra + 8];
            scl[i][0] = 1.f / (float)max(d0, 1);
            scl[i][1] = 1.f / (float)max(d1, 1);
        }
    }

    #pragma unroll
    for (int j = 0; j < 8; j++) {
        int col = nw + j * 8 + 2 * tg;
        float2 bv = *(const float2*)(bias + col);
        #pragma unroll
        for (int i = 0; i < 2; i++) {
            int ra = row0 + mw + i * 16 + g;
            float2 r0v = __ldg((const float2*)(res + (size_t)ra * HH + col));
            float2 r1v = __ldg((const float2*)(res + (size_t)(ra + 8) * HH + col));
            float2 o0, o1;
            o0.x = r0v.x + fmaxf(acc[i][j][0] * scl[i][0] + bv.x, 0.f);
            o0.y = r0v.y + fmaxf(acc[i][j][1] * scl[i][0] + bv.y, 0.f);
            o1.x = r1v.x + fmaxf(acc[i][j][2] * scl[i][1] + bv.x, 0.f);
            o1.y = r1v.y + fmaxf(acc[i][j][3] * scl[i][1] + bv.y, 0.f);
            *(float2*)(out + (size_t)ra * HH + col) = o0;
            *(float2*)(out + (size_t)(ra + 8) * HH + col) = o1;
        }
    }
}

// ---------------- launch (single stream) ----------------
extern "C" void kernel_launch(void* const* d_in, const int* in_sizes, int n_in,
                              void* d_out, int out_size) {
    const float* router_feat  = (const float*)d_in[0];
    const float* packet_feat  = (const float*)d_in[1];
    const float* W_r          = (const float*)d_in[2];
    const float* b_r          = (const float*)d_in[3];
    const float* W_p          = (const float*)d_in[4];
    const float* b_p          = (const float*)d_in[5];
    const int*   pass_src     = (const int*)d_in[6];
    const int*   pass_dst     = (const int*)d_in[7];
    const int*   transfer_src = (const int*)d_in[8];
    const int*   transfer_dst = (const int*)d_in[9];
    const int*   connect_src  = (const int*)d_in[10];
    const int*   connect_dst  = (const int*)d_in[11];
    float* out = (float*)d_out;

    int* degbase;
    cudaGetSymbolAddress((void**)&degbase, g_deg);
    cudaMemsetAsync(degbase, 0, 3 * NN * sizeof(int), 0);

    k_f16<<<2 * NN * HH / 8 / 256, 256>>>(router_feat, packet_feat);
    k_w16<<<96, 256>>>(W_r, W_p);
    k_hist<<<(3 * EE + 255) / 256, 256>>>(pass_dst, connect_dst, transfer_dst);
    k_scan1<<<768, 256>>>();
    k_scan2<<<3, 256>>>();
    k_scan3<<<3 * NN / 256, 256>>>();
    k_fill<<<(3 * EE + 255) / 256, 256>>>(pass_src, pass_dst, connect_src, connect_dst,
                                          transfer_src, transfer_dst);
    k_gather16<<<3 * NN * 16 / 256, 256>>>();
    k_gemm_f16<256, true ><<<NN / 128, 256>>>(router_feat, b_r, out);
    k_gemm_f16<128, false><<<NN / 128, 256>>>(packet_feat, b_p, out + (size_t)NN * HH);
}

// round 8
// speedup vs baseline: 2.4653x; 1.0035x over previous
#include <cuda_runtime.h>
#include <cuda_fp16.h>
#include <cstdint>

#define NN 65536
#define HH 128
#define EE 524288

// ---------------- static scratch ----------------
__device__ int    g_deg[3][NN];
__device__ int    g_rowptr[3][NN + 1];
__device__ int    g_cursor[3][NN];
__device__ int    g_csum[3][256];
__device__ int    g_col[3][EE];
__device__ __half g_h16[3][NN * HH];
__device__ __half g_rf16[NN * HH];
__device__ __half g_pf16[NN * HH];
__device__ __half g_wr16[HH * 256];
__device__ __half g_wp16[HH * HH];

// ---------------- fp16 conversion: feature tables ----------------
__global__ void k_f16(const float* __restrict__ rf, const float* __restrict__ pf) {
    int i = blockIdx.x * blockDim.x + threadIdx.x;   // 8 floats per thread
    const int half_total = NN * HH / 8;
    const float4* src;
    __half* dst;
    int base;
    if (i < half_total) { src = (const float4*)rf; dst = g_rf16; base = i; }
    else                { src = (const float4*)pf; dst = g_pf16; base = i - half_total; }
    float4 v0 = __ldg(src + base * 2);
    float4 v1 = __ldg(src + base * 2 + 1);
    __half2 h[4];
    h[0] = __floats2half2_rn(v0.x, v0.y);
    h[1] = __floats2half2_rn(v0.z, v0.w);
    h[2] = __floats2half2_rn(v1.x, v1.y);
    h[3] = __floats2half2_rn(v1.z, v1.w);
    *(uint4*)(dst + (size_t)base * 8) = *(uint4*)h;
}

// ---------------- fp16 conversion: weights ----------------
__global__ void k_w16(const float* __restrict__ Wr, const float* __restrict__ Wp) {
    int i = blockIdx.x * blockDim.x + threadIdx.x;
    if (i < 16384) {
        float2 v = __ldg((const float2*)Wr + i);
        *(__half2*)(g_wr16 + i * 2) = __floats2half2_rn(v.x, v.y);
    } else if (i < 24576) {
        int j = i - 16384;
        float2 v = __ldg((const float2*)Wp + j);
        *(__half2*)(g_wp16 + j * 2) = __floats2half2_rn(v.x, v.y);
    }
}

// ---------------- CSR build (4 edges/thread, vectorized) ----------------
__global__ void k_hist(const int* __restrict__ pass_dst,
                       const int* __restrict__ connect_dst,
                       const int* __restrict__ transfer_dst) {
    int q = blockIdx.x * blockDim.x + threadIdx.x;   // quad index
    if (q >= 3 * EE / 4) return;
    int r = q / (EE / 4), e4 = q - r * (EE / 4);
    const int* dst = (r == 0) ? pass_dst : (r == 1) ? connect_dst : transfer_dst;
    int4 d = __ldg((const int4*)dst + e4);
    atomicAdd(&g_deg[r][d.x], 1);
    atomicAdd(&g_deg[r][d.y], 1);
    atomicAdd(&g_deg[r][d.z], 1);
    atomicAdd(&g_deg[r][d.w], 1);
}

__global__ void k_scan1() {
    int b = blockIdx.x;
    int r = b >> 8, ch = b & 255;
    int t = threadIdx.x;
    int idx = ch * 256 + t;
    int v = g_deg[r][idx];
    __shared__ int sm[256];
    sm[t] = v;
    __syncthreads();
    #pragma unroll
    for (int off = 1; off < 256; off <<= 1) {
        int u = (t >= off) ? sm[t - off] : 0;
        __syncthreads();
        sm[t] += u;
        __syncthreads();
    }
    g_rowptr[r][idx] = sm[t] - v;
    if (t == 255) g_csum[r][ch] = sm[t];
}

__global__ void k_scan2() {
    int r = blockIdx.x;
    int t = threadIdx.x;
    int v = g_csum[r][t];
    __shared__ int sm[256];
    sm[t] = v;
    __syncthreads();
    #pragma unroll
    for (int off = 1; off < 256; off <<= 1) {
        int u = (t >= off) ? sm[t - off] : 0;
        __syncthreads();
        sm[t] += u;
        __syncthreads();
    }
    g_csum[r][t] = sm[t] - v;
    if (t == 255) g_rowptr[r][NN] = sm[t];
}

__global__ void k_scan3() {
    int i = blockIdx.x * blockDim.x + threadIdx.x;
    if (i >= 3 * NN) return;
    int r = i >> 16, n = i & (NN - 1);
    int val = g_rowptr[r][n] + g_csum[r][n >> 8];
    g_rowptr[r][n] = val;
    g_cursor[r][n] = val;
}

__global__ void k_fill(const int* __restrict__ pass_src, const int* __restrict__ pass_dst,
                       const int* __restrict__ connect_src, const int* __restrict__ connect_dst,
                       const int* __restrict__ transfer_src, const int* __restrict__ transfer_dst) {
    int q = blockIdx.x * blockDim.x + threadIdx.x;   // quad index
    if (q >= 3 * EE / 4) return;
    int r = q / (EE / 4), e4 = q - r * (EE / 4);
    const int *src, *dst;
    if (r == 0)      { src = pass_src;     dst = pass_dst; }
    else if (r == 1) { src = connect_src;  dst = connect_dst; }
    else             { src = transfer_src; dst = transfer_dst; }
    int4 d = __ldg((const int4*)dst + e4);
    int4 s = __ldg((const int4*)src + e4);
    int p0 = atomicAdd(&g_cursor[r][d.x], 1);
    int p1 = atomicAdd(&g_cursor[r][d.y], 1);
    int p2 = atomicAdd(&g_cursor[r][d.z], 1);
    int p3 = atomicAdd(&g_cursor[r][d.w], 1);
    g_col[r][p0] = s.x;
    g_col[r][p1] = s.y;
    g_col[r][p2] = s.z;
    g_col[r][p3] = s.w;
}

// ---------------- gather: full warp per node, 2 edges in parallel ----------------
#define ACCP(P) { float2 f; \
    f = __half22float2((P)[0]); a0.x += f.x; a0.y += f.y; \
    f = __half22float2((P)[1]); a1.x += f.x; a1.y += f.y; \
    f = __half22float2((P)[2]); a2.x += f.x; a2.y += f.y; \
    f = __half22float2((P)[3]); a3.x += f.x; a3.y += f.y; }

__global__ void k_gather16(int rbase, int nwarps) {
    int w = (blockIdx.x * blockDim.x + threadIdx.x) >> 5;
    if (w >= nwarps) return;
    int lane = threadIdx.x & 31;
    int e2 = lane >> 4, ln = lane & 15;
    int r = rbase + (w >> 16);
    int i = w & (NN - 1);
    const uint4* tab = (const uint4*)((r == 0) ? g_pf16 : g_rf16);

    int s = g_rowptr[r][i], e = g_rowptr[r][i + 1];
    float2 a0 = {0,0}, a1 = {0,0}, a2 = {0,0}, a3 = {0,0};
    int k = s + e2;
    for (; k + 2 < e; k += 4) {       // this half handles edges k and k+2
        int c0 = g_col[r][k], c1 = g_col[r][k + 2];
        uint4 v0 = __ldg(tab + (size_t)c0 * 16 + ln);
        uint4 v1 = __ldg(tab + (size_t)c1 * 16 + ln);
        const __half2* p0 = (const __half2*)&v0;
        const __half2* p1 = (const __half2*)&v1;
        ACCP(p0); ACCP(p1);
    }
    for (; k < e; k += 2) {
        int c0 = g_col[r][k];
        uint4 v0 = __ldg(tab + (size_t)c0 * 16 + ln);
        const __half2* p0 = (const __half2*)&v0;
        ACCP(p0);
    }
    // combine the two halves (feature chunks align across halves)
    a0.x += __shfl_xor_sync(0xffffffffu, a0.x, 16);
    a0.y += __shfl_xor_sync(0xffffffffu, a0.y, 16);
    a1.x += __shfl_xor_sync(0xffffffffu, a1.x, 16);
    a1.y += __shfl_xor_sync(0xffffffffu, a1.y, 16);
    a2.x += __shfl_xor_sync(0xffffffffu, a2.x, 16);
    a2.y += __shfl_xor_sync(0xffffffffu, a2.y, 16);
    a3.x += __shfl_xor_sync(0xffffffffu, a3.x, 16);
    a3.y += __shfl_xor_sync(0xffffffffu, a3.y, 16);
    if (e2 == 0) {
        __half2 h[4];
        h[0] = __floats2half2_rn(a0.x, a0.y);
        h[1] = __floats2half2_rn(a1.x, a1.y);
        h[2] = __floats2half2_rn(a2.x, a2.y);
        h[3] = __floats2half2_rn(a3.x, a3.y);
        *((uint4*)(g_h16[r] + (size_t)i * HH) + ln) = *(uint4*)h;
    }
}

// ---------------- fp16 tensor-core fused linear + ReLU + residual ----------------
__device__ __forceinline__ void mma_f16(float* d, const uint32_t* a, const uint32_t* b) {
    asm volatile(
        "mma.sync.aligned.m16n8k16.row.col.f32.f16.f16.f32 "
        "{%0,%1,%2,%3},{%4,%5,%6,%7},{%8,%9},{%0,%1,%2,%3};"
        : "+f"(d[0]), "+f"(d[1]), "+f"(d[2]), "+f"(d[3])
        : "r"(a[0]), "r"(a[1]), "r"(a[2]), "r"(a[3]), "r"(b[0]), "r"(b[1]));
}

#define KC 64
#define XSH 72

template<int KTOT, bool ROUTER>
__global__ void __launch_bounds__(256, 2) k_gemm_f16(const float* __restrict__ res,
                                                     const float* __restrict__ bias,
                                                     float* __restrict__ out) {
    __shared__ __half sX[128 * XSH];
    __shared__ __half sW[128 * XSH];

    const int t = threadIdx.x;
    const int warp = t >> 5, lane = t & 31;
    const int g = lane >> 2, tg = lane & 3;
    const int mw = (warp & 3) * 32;
    const int nw = (warp >> 2) * 64;
    const int row0 = blockIdx.x * 128;
    const __half* Wh = ROUTER ? g_wr16 : g_wp16;

    float acc[2][8][4];
    #pragma unroll
    for (int i = 0; i < 2; i++)
        #pragma unroll
        for (int j = 0; j < 8; j++)
            #pragma unroll
            for (int q = 0; q < 4; q++) acc[i][j][q] = 0.f;

    #pragma unroll
    for (int c = 0; c < KTOT / KC; c++) {
        const __half* xsrc;
        int koff;
        if (ROUTER) { xsrc = (c < 2) ? g_h16[0] : g_h16[1]; koff = (c & 1) * KC; }
        else        { xsrc = g_h16[2];                       koff = c * KC; }

        __syncthreads();
        #pragma unroll
        for (int it = 0; it < 4; it++) {
            int idx = it * 256 + t;
            int row = idx >> 3, c8 = idx & 7;
            uint4 xv = __ldg((const uint4*)(xsrc + (size_t)(row0 + row) * HH + koff) + c8);
            *(uint4*)&sX[row * XSH + c8 * 8] = xv;
            uint4 wv = __ldg((const uint4*)(Wh + (size_t)row * KTOT + c * KC) + c8);
            *(uint4*)&sW[row * XSH + c8 * 8] = wv;
        }
        __syncthreads();

        #pragma unroll
        for (int ks = 0; ks < KC / 16; ks++) {
            int k0 = ks * 16;
            uint32_t a[2][4], b[8][2];
            #pragma unroll
            for (int i = 0; i < 2; i++) {
                int r = mw + i * 16 + g;
                a[i][0] = *(const uint32_t*)&sX[r * XSH + k0 + 2 * tg];
                a[i][1] = *(const uint32_t*)&sX[(r + 8) * XSH + k0 + 2 * tg];
                a[i][2] = *(const uint32_t*)&sX[r * XSH + k0 + 8 + 2 * tg];
                a[i][3] = *(const uint32_t*)&sX[(r + 8) * XSH + k0 + 8 + 2 * tg];
            }
            #pragma unroll
            for (int j = 0; j < 8; j++) {
                int n = nw + j * 8 + g;
                b[j][0] = *(const uint32_t*)&sW[n * XSH + k0 + 2 * tg];
                b[j][1] = *(const uint32_t*)&sW[n * XSH + k0 + 8 + 2 * tg];
            }
            #pragma unroll
            for (int i = 0; i < 2; i++)
                #pragma unroll
                for (int j = 0; j < 8; j++)
                    mma_f16(acc[i][j], a[i], b[j]);
        }
    }

    float scl[2][2];
    #pragma unroll
    for (int i = 0; i < 2; i++) {
        if (ROUTER) { scl[i][0] = 1.f; scl[i][1] = 1.f; }
        else {
            int ra = row0 + mw + i * 16 + g;
            int d0 = g_rowptr[2][ra + 1] - g_rowptr[2][ra];
            int d1 = g_rowptr[2][ra + 9] - g_rowptr[2][ra + 8];
            scl[i][0] = 1.f / (float)max(d0, 1);
            scl[i][1] = 1.f / (float)max(d1, 1);
        }
    }

    #pragma unroll
    for (int j = 0; j < 8; j++) {
        int col = nw + j * 8 + 2 * tg;
        float2 bv = *(const float2*)(bias + col);
        #pragma unroll
        for (int i = 0; i < 2; i++) {
            int ra = row0 + mw + i * 16 + g;
            float2 r0v = __ldg((const float2*)(res + (size_t)ra * HH + col));
            float2 r1v = __ldg((const float2*)(res + (size_t)(ra + 8) * HH + col));
            float2 o0, o1;
            o0.x = r0v.x + fmaxf(acc[i][j][0] * scl[i][0] + bv.x, 0.f);
            o0.y = r0v.y + fmaxf(acc[i][j][1] * scl[i][0] + bv.y, 0.f);
            o1.x = r1v.x + fmaxf(acc[i][j][2] * scl[i][1] + bv.x, 0.f);
            o1.y = r1v.y + fmaxf(acc[i][j][3] * scl[i][1] + bv.y, 0.f);
            *(float2*)(out + (size_t)ra * HH + col) = o0;
            *(float2*)(out + (size_t)(ra + 8) * HH + col) = o1;
        }
    }
}

// ---------------- launch: fork-join overlap ----------------
extern "C" void kernel_launch(void* const* d_in, const int* in_sizes, int n_in,
                              void* d_out, int out_size) {
    const float* router_feat  = (const float*)d_in[0];
    const float* packet_feat  = (const float*)d_in[1];
    const float* W_r          = (const float*)d_in[2];
    const float* b_r          = (const float*)d_in[3];
    const float* W_p          = (const float*)d_in[4];
    const float* b_p          = (const float*)d_in[5];
    const int*   pass_src     = (const int*)d_in[6];
    const int*   pass_dst     = (const int*)d_in[7];
    const int*   transfer_src = (const int*)d_in[8];
    const int*   transfer_dst = (const int*)d_in[9];
    const int*   connect_src  = (const int*)d_in[10];
    const int*   connect_dst  = (const int*)d_in[11];
    float* out = (float*)d_out;

    static cudaStream_t s1 = nullptr;
    static cudaEvent_t evFork, evF16, evCSR, evJoin;
    static int* degbase = nullptr;
    if (!s1) {
        cudaStreamCreateWithFlags(&s1, cudaStreamNonBlocking);
        cudaEventCreateWithFlags(&evFork, cudaEventDisableTiming);
        cudaEventCreateWithFlags(&evF16,  cudaEventDisableTiming);
        cudaEventCreateWithFlags(&evCSR,  cudaEventDisableTiming);
        cudaEventCreateWithFlags(&evJoin, cudaEventDisableTiming);
        cudaGetSymbolAddress((void**)&degbase, g_deg);
    }

    // fork
    cudaEventRecord(evFork, 0);
    cudaStreamWaitEvent(s1, evFork, 0);

    // s1: fp16 conversions (independent of CSR)
    k_f16<<<2 * NN * HH / 8 / 256, 256, 0, s1>>>(router_feat, packet_feat);
    k_w16<<<96, 256, 0, s1>>>(W_r, W_p);
    cudaEventRecord(evF16, s1);

    // s0: CSR build
    cudaMemsetAsync(degbase, 0, 3 * NN * sizeof(int), 0);
    k_hist<<<(3 * EE / 4 + 255) / 256, 256>>>(pass_dst, connect_dst, transfer_dst);
    k_scan1<<<768, 256>>>();
    k_scan2<<<3, 256>>>();
    k_scan3<<<3 * NN / 256, 256>>>();
    k_fill<<<(3 * EE / 4 + 255) / 256, 256>>>(pass_src, pass_dst, connect_src, connect_dst,
                                              transfer_src, transfer_dst);
    cudaEventRecord(evCSR, 0);

    // s0: router chain (needs f16 + CSR)
    cudaStreamWaitEvent(0, evF16, 0);
    k_gather16<<<2 * NN * 32 / 256, 256>>>(0, 2 * NN);
    k_gemm_f16<256, true ><<<NN / 128, 256>>>(router_feat, b_r, out);

    // s1: packet chain (needs f16 [in-order on s1] + CSR)
    cudaStreamWaitEvent(s1, evCSR, 0);
    k_gather16<<<NN * 32 / 256, 256, 0, s1>>>(2, NN);
    k_gemm_f16<128, false><<<NN / 128, 256, 0, s1>>>(packet_feat, b_p, out + (size_t)NN * HH);

    // join
    cudaEventRecord(evJoin, s1);
    cudaStreamWaitEvent(0, evJoin, 0);
}

// round 9
// speedup vs baseline: 2.6073x; 1.0576x over previous
#include <cuda_runtime.h>
#include <cuda_fp16.h>
#include <cstdint>

#define NN 65536
#define HH 128
#define EE 524288

// ---------------- static scratch ----------------
__device__ int    g_deg[3][NN];
__device__ int    g_rowptr[3][NN + 1];
__device__ int    g_cursor[3][NN];
__device__ int    g_csum[3][256];
__device__ int    g_col[3][EE];
__device__ __half g_h16[3][NN * HH];   // 0: A = pf@Wr1^T, 1: B = rf@Wr2^T, 2: C = rf@Wp^T
__device__ __half g_rf16[NN * HH];
__device__ __half g_pf16[NN * HH];
__device__ __half g_wr16[HH * 256];
__device__ __half g_wp16[HH * HH];

// ---------------- fp16 conversion: feature tables ----------------
__global__ void k_f16(const float* __restrict__ rf, const float* __restrict__ pf) {
    int i = blockIdx.x * blockDim.x + threadIdx.x;   // 8 floats per thread
    const int half_total = NN * HH / 8;
    const float4* src;
    __half* dst;
    int base;
    if (i < half_total) { src = (const float4*)rf; dst = g_rf16; base = i; }
    else                { src = (const float4*)pf; dst = g_pf16; base = i - half_total; }
    float4 v0 = __ldg(src + base * 2);
    float4 v1 = __ldg(src + base * 2 + 1);
    __half2 h[4];
    h[0] = __floats2half2_rn(v0.x, v0.y);
    h[1] = __floats2half2_rn(v0.z, v0.w);
    h[2] = __floats2half2_rn(v1.x, v1.y);
    h[3] = __floats2half2_rn(v1.z, v1.w);
    *(uint4*)(dst + (size_t)base * 8) = *(uint4*)h;
}

// ---------------- fp16 conversion: weights ----------------
__global__ void k_w16(const float* __restrict__ Wr, const float* __restrict__ Wp) {
    int i = blockIdx.x * blockDim.x + threadIdx.x;
    if (i < 16384) {
        float2 v = __ldg((const float2*)Wr + i);
        *(__half2*)(g_wr16 + i * 2) = __floats2half2_rn(v.x, v.y);
    } else if (i < 24576) {
        int j = i - 16384;
        float2 v = __ldg((const float2*)Wp + j);
        *(__half2*)(g_wp16 + j * 2) = __floats2half2_rn(v.x, v.y);
    }
}

// ---------------- CSR build ----------------
__global__ void k_hist(const int* __restrict__ pass_dst,
                       const int* __restrict__ connect_dst,
                       const int* __restrict__ transfer_dst) {
    int q = blockIdx.x * blockDim.x + threadIdx.x;   // quad index
    if (q >= 3 * EE / 4) return;
    int r = q / (EE / 4), e4 = q - r * (EE / 4);
    const int* dst = (r == 0) ? pass_dst : (r == 1) ? connect_dst : transfer_dst;
    int4 d = __ldg((const int4*)dst + e4);
    atomicAdd(&g_deg[r][d.x], 1);
    atomicAdd(&g_deg[r][d.y], 1);
    atomicAdd(&g_deg[r][d.z], 1);
    atomicAdd(&g_deg[r][d.w], 1);
}

__global__ void k_scan1() {
    int b = blockIdx.x;
    int r = b >> 8, ch = b & 255;
    int t = threadIdx.x;
    int idx = ch * 256 + t;
    int v = g_deg[r][idx];
    __shared__ int sm[256];
    sm[t] = v;
    __syncthreads();
    #pragma unroll
    for (int off = 1; off < 256; off <<= 1) {
        int u = (t >= off) ? sm[t - off] : 0;
        __syncthreads();
        sm[t] += u;
        __syncthreads();
    }
    g_rowptr[r][idx] = sm[t] - v;
    if (t == 255) g_csum[r][ch] = sm[t];
}

__global__ void k_scan2() {
    int r = blockIdx.x;
    int t = threadIdx.x;
    int v = g_csum[r][t];
    __shared__ int sm[256];
    sm[t] = v;
    __syncthreads();
    #pragma unroll
    for (int off = 1; off < 256; off <<= 1) {
        int u = (t >= off) ? sm[t - off] : 0;
        __syncthreads();
        sm[t] += u;
        __syncthreads();
    }
    g_csum[r][t] = sm[t] - v;
    if (t == 255) g_rowptr[r][NN] = sm[t];
}

__global__ void k_scan3() {
    int i = blockIdx.x * blockDim.x + threadIdx.x;
    if (i >= 3 * NN) return;
    int r = i >> 16, n = i & (NN - 1);
    int val = g_rowptr[r][n] + g_csum[r][n >> 8];
    g_rowptr[r][n] = val;
    g_cursor[r][n] = val;
}

__global__ void k_fill(const int* __restrict__ pass_src, const int* __restrict__ pass_dst,
                       const int* __restrict__ connect_src, const int* __restrict__ connect_dst,
                       const int* __restrict__ transfer_src, const int* __restrict__ transfer_dst) {
    int q = blockIdx.x * blockDim.x + threadIdx.x;   // quad index
    if (q >= 3 * EE / 4) return;
    int r = q / (EE / 4), e4 = q - r * (EE / 4);
    const int *src, *dst;
    if (r == 0)      { src = pass_src;     dst = pass_dst; }
    else if (r == 1) { src = connect_src;  dst = connect_dst; }
    else             { src = transfer_src; dst = transfer_dst; }
    int4 d = __ldg((const int4*)dst + e4);
    int4 s = __ldg((const int4*)src + e4);
    int p0 = atomicAdd(&g_cursor[r][d.x], 1);
    int p1 = atomicAdd(&g_cursor[r][d.y], 1);
    int p2 = atomicAdd(&g_cursor[r][d.z], 1);
    int p3 = atomicAdd(&g_cursor[r][d.w], 1);
    g_col[r][p0] = s.x;
    g_col[r][p1] = s.y;
    g_col[r][p2] = s.z;
    g_col[r][p3] = s.w;
}

// ---------------- fp16 tensor-core plain GEMM: Y[i][n] = sum_k X[i][k]*W[n][WOFF+k], fp16 out ----------------
__device__ __forceinline__ void mma_f16(float* d, const uint32_t* a, const uint32_t* b) {
    asm volatile(
        "mma.sync.aligned.m16n8k16.row.col.f32.f16.f16.f32 "
        "{%0,%1,%2,%3},{%4,%5,%6,%7},{%8,%9},{%0,%1,%2,%3};"
        : "+f"(d[0]), "+f"(d[1]), "+f"(d[2]), "+f"(d[3])
        : "r"(a[0]), "r"(a[1]), "r"(a[2]), "r"(a[3]), "r"(b[0]), "r"(b[1]));
}

#define KC 64
#define XSH 72   // padded smem stride in halves (144B rows, conflict-free)

template<int LDW, int WOFF>
__global__ void __launch_bounds__(256, 2) k_gemm_h(const __half* __restrict__ X,
                                                   const __half* __restrict__ W,
                                                   __half* __restrict__ Y) {
    __shared__ __half sX[128 * XSH];
    __shared__ __half sW[128 * XSH];

    const int t = threadIdx.x;
    const int warp = t >> 5, lane = t & 31;
    const int g = lane >> 2, tg = lane & 3;
    const int mw = (warp & 3) * 32;
    const int nw = (warp >> 2) * 64;
    const int row0 = blockIdx.x * 128;

    float acc[2][8][4];
    #pragma unroll
    for (int i = 0; i < 2; i++)
        #pragma unroll
        for (int j = 0; j < 8; j++)
            #pragma unroll
            for (int q = 0; q < 4; q++) acc[i][j][q] = 0.f;

    #pragma unroll
    for (int c = 0; c < HH / KC; c++) {
        __syncthreads();
        #pragma unroll
        for (int it = 0; it < 4; it++) {
            int idx = it * 256 + t;
            int row = idx >> 3, c8 = idx & 7;
            uint4 xv = __ldg((const uint4*)(X + (size_t)(row0 + row) * HH + c * KC) + c8);
            *(uint4*)&sX[row * XSH + c8 * 8] = xv;
            uint4 wv = __ldg((const uint4*)(W + (size_t)row * LDW + WOFF + c * KC) + c8);
            *(uint4*)&sW[row * XSH + c8 * 8] = wv;
        }
        __syncthreads();

        #pragma unroll
        for (int ks = 0; ks < KC / 16; ks++) {
            int k0 = ks * 16;
            uint32_t a[2][4], b[8][2];
            #pragma unroll
            for (int i = 0; i < 2; i++) {
                int r = mw + i * 16 + g;
                a[i][0] = *(const uint32_t*)&sX[r * XSH + k0 + 2 * tg];
                a[i][1] = *(const uint32_t*)&sX[(r + 8) * XSH + k0 + 2 * tg];
                a[i][2] = *(const uint32_t*)&sX[r * XSH + k0 + 8 + 2 * tg];
                a[i][3] = *(const uint32_t*)&sX[(r + 8) * XSH + k0 + 8 + 2 * tg];
            }
            #pragma unroll
            for (int j = 0; j < 8; j++) {
                int n = nw + j * 8 + g;
                b[j][0] = *(const uint32_t*)&sW[n * XSH + k0 + 2 * tg];
                b[j][1] = *(const uint32_t*)&sW[n * XSH + k0 + 8 + 2 * tg];
            }
            #pragma unroll
            for (int i = 0; i < 2; i++)
                #pragma unroll
                for (int j = 0; j < 8; j++)
                    mma_f16(acc[i][j], a[i], b[j]);
        }
    }

    #pragma unroll
    for (int j = 0; j < 8; j++) {
        int col = nw + j * 8 + 2 * tg;
        #pragma unroll
        for (int i = 0; i < 2; i++) {
            int ra = row0 + mw + i * 16 + g;
            *(__half2*)(Y + (size_t)ra * HH + col)       = __floats2half2_rn(acc[i][j][0], acc[i][j][1]);
            *(__half2*)(Y + (size_t)(ra + 8) * HH + col) = __floats2half2_rn(acc[i][j][2], acc[i][j][3]);
        }
    }
}

// ---------------- fused gather + epilogue ----------------
#define ACCP(P) { float2 f; \
    f = __half22float2((P)[0]); a0.x += f.x; a0.y += f.y; \
    f = __half22float2((P)[1]); a1.x += f.x; a1.y += f.y; \
    f = __half22float2((P)[2]); a2.x += f.x; a2.y += f.y; \
    f = __half22float2((P)[3]); a3.x += f.x; a3.y += f.y; }

#define GATHER_REL(TAB, R) { \
    int s = g_rowptr[R][w], e = g_rowptr[R][w + 1]; \
    int k = s + e2; \
    for (; k + 2 < e; k += 4) { \
        int c0 = g_col[R][k], c1 = g_col[R][k + 2]; \
        uint4 v0 = __ldg((TAB) + (size_t)c0 * 16 + ln); \
        uint4 v1 = __ldg((TAB) + (size_t)c1 * 16 + ln); \
        const __half2* p0 = (const __half2*)&v0; \
        const __half2* p1 = (const __half2*)&v1; \
        ACCP(p0); ACCP(p1); \
    } \
    for (; k < e; k += 2) { \
        int c0 = g_col[R][k]; \
        uint4 v0 = __ldg((TAB) + (size_t)c0 * 16 + ln); \
        const __half2* p0 = (const __half2*)&v0; \
        ACCP(p0); \
    } \
}

#define SHFL_COMBINE() { \
    a0.x += __shfl_xor_sync(0xffffffffu, a0.x, 16); \
    a0.y += __shfl_xor_sync(0xffffffffu, a0.y, 16); \
    a1.x += __shfl_xor_sync(0xffffffffu, a1.x, 16); \
    a1.y += __shfl_xor_sync(0xffffffffu, a1.y, 16); \
    a2.x += __shfl_xor_sync(0xffffffffu, a2.x, 16); \
    a2.y += __shfl_xor_sync(0xffffffffu, a2.y, 16); \
    a3.x += __shfl_xor_sync(0xffffffffu, a3.x, 16); \
    a3.y += __shfl_xor_sync(0xffffffffu, a3.y, 16); \
}

// router: out = rf + relu(sum_pass A[src] + sum_connect B[src] + br)
__global__ void k_gather_router(const float* __restrict__ rf, const float* __restrict__ br,
                                float* __restrict__ out) {
    int w = (blockIdx.x * blockDim.x + threadIdx.x) >> 5;
    if (w >= NN) return;
    int lane = threadIdx.x & 31;
    int e2 = lane >> 4, ln = lane & 15;     // lane covers features [ln*8, ln*8+8)
    const uint4* A = (const uint4*)g_h16[0];
    const uint4* B = (const uint4*)g_h16[1];

    float2 a0 = {0,0}, a1 = {0,0}, a2 = {0,0}, a3 = {0,0};
    GATHER_REL(A, 0);
    GATHER_REL(B, 1);
    SHFL_COMBINE();
    if (e2 == 0) {
        float4 b0 = __ldg((const float4*)br + ln * 2);
        float4 b1 = __ldg((const float4*)br + ln * 2 + 1);
        float4 r0 = __ldg((const float4*)(rf + (size_t)w * HH) + ln * 2);
        float4 r1 = __ldg((const float4*)(rf + (size_t)w * HH) + ln * 2 + 1);
        float4 o0, o1;
        o0.x = r0.x + fmaxf(a0.x + b0.x, 0.f);
        o0.y = r0.y + fmaxf(a0.y + b0.y, 0.f);
        o0.z = r0.z + fmaxf(a1.x + b0.z, 0.f);
        o0.w = r0.w + fmaxf(a1.y + b0.w, 0.f);
        o1.x = r1.x + fmaxf(a2.x + b1.x, 0.f);
        o1.y = r1.y + fmaxf(a2.y + b1.y, 0.f);
        o1.z = r1.z + fmaxf(a3.x + b1.z, 0.f);
        o1.w = r1.w + fmaxf(a3.y + b1.w, 0.f);
        ((float4*)(out + (size_t)w * HH))[ln * 2]     = o0;
        ((float4*)(out + (size_t)w * HH))[ln * 2 + 1] = o1;
    }
}

// packet: out = pf + relu(mean_transfer C[src] + bp)
__global__ void k_gather_packet(const float* __restrict__ pf, const float* __restrict__ bp,
                                float* __restrict__ out) {
    int w = (blockIdx.x * blockDim.x + threadIdx.x) >> 5;
    if (w >= NN) return;
    int lane = threadIdx.x & 31;
    int e2 = lane >> 4, ln = lane & 15;
    const uint4* C = (const uint4*)g_h16[2];

    float2 a0 = {0,0}, a1 = {0,0}, a2 = {0,0}, a3 = {0,0};
    GATHER_REL(C, 2);
    SHFL_COMBINE();
    if (e2 == 0) {
        int deg = g_rowptr[2][w + 1] - g_rowptr[2][w];
        float scl = 1.0f / (float)max(deg, 1);
        float4 b0 = __ldg((const float4*)bp + ln * 2);
        float4 b1 = __ldg((const float4*)bp + ln * 2 + 1);
        float4 r0 = __ldg((const float4*)(pf + (size_t)w * HH) + ln * 2);
        float4 r1 = __ldg((const float4*)(pf + (size_t)w * HH) + ln * 2 + 1);
        float4 o0, o1;
        o0.x = r0.x + fmaxf(a0.x * scl + b0.x, 0.f);
        o0.y = r0.y + fmaxf(a0.y * scl + b0.y, 0.f);
        o0.z = r0.z + fmaxf(a1.x * scl + b0.z, 0.f);
        o0.w = r0.w + fmaxf(a1.y * scl + b0.w, 0.f);
        o1.x = r1.x + fmaxf(a2.x * scl + b1.x, 0.f);
        o1.y = r1.y + fmaxf(a2.y * scl + b1.y, 0.f);
        o1.z = r1.z + fmaxf(a3.x * scl + b1.z, 0.f);
        o1.w = r1.w + fmaxf(a3.y * scl + b1.w, 0.f);
        ((float4*)(out + (size_t)w * HH))[ln * 2]     = o0;
        ((float4*)(out + (size_t)w * HH))[ln * 2 + 1] = o1;
    }
}

// ---------------- launch: GEMMs hidden under CSR build ----------------
extern "C" void kernel_launch(void* const* d_in, const int* in_sizes, int n_in,
                              void* d_out, int out_size) {
    const float* router_feat  = (const float*)d_in[0];
    const float* packet_feat  = (const float*)d_in[1];
    const float* W_r          = (const float*)d_in[2];
    const float* b_r          = (const float*)d_in[3];
    const float* W_p          = (const float*)d_in[4];
    const float* b_p          = (const float*)d_in[5];
    const int*   pass_src     = (const int*)d_in[6];
    const int*   pass_dst     = (const int*)d_in[7];
    const int*   transfer_src = (const int*)d_in[8];
    const int*   transfer_dst = (const int*)d_in[9];
    const int*   connect_src  = (const int*)d_in[10];
    const int*   connect_dst  = (const int*)d_in[11];
    float* out = (float*)d_out;

    static cudaStream_t s1 = nullptr;
    static cudaEvent_t evFork, evG, evCSR, evJoin;
    static int* degbase = nullptr;
    static __half *hA, *hB, *hC, *hRF, *hPF, *hWR, *hWP;
    if (!s1) {
        cudaStreamCreateWithFlags(&s1, cudaStreamNonBlocking);
        cudaEventCreateWithFlags(&evFork, cudaEventDisableTiming);
        cudaEventCreateWithFlags(&evG,    cudaEventDisableTiming);
        cudaEventCreateWithFlags(&evCSR,  cudaEventDisableTiming);
        cudaEventCreateWithFlags(&evJoin, cudaEventDisableTiming);
        cudaGetSymbolAddress((void**)&degbase, g_deg);
        __half* h16base;
        cudaGetSymbolAddress((void**)&h16base, g_h16);
        hA = h16base;
        hB = h16base + (size_t)NN * HH;
        hC = h16base + 2 * (size_t)NN * HH;
        cudaGetSymbolAddress((void**)&hRF, g_rf16);
        cudaGetSymbolAddress((void**)&hPF, g_pf16);
        cudaGetSymbolAddress((void**)&hWR, g_wr16);
        cudaGetSymbolAddress((void**)&hWP, g_wp16);
    }

    // fork
    cudaEventRecord(evFork, 0);
    cudaStreamWaitEvent(s1, evFork, 0);

    // s1: conversions + the three dense transform GEMMs (independent of graph)
    k_f16<<<2 * NN * HH / 8 / 256, 256, 0, s1>>>(router_feat, packet_feat);
    k_w16<<<96, 256, 0, s1>>>(W_r, W_p);
    k_gemm_h<256, 0  ><<<NN / 128, 256, 0, s1>>>(hPF, hWR, hA);   // A = pf @ Wr[:, :128]^T
    k_gemm_h<256, 128><<<NN / 128, 256, 0, s1>>>(hRF, hWR, hB);   // B = rf @ Wr[:, 128:]^T
    cudaEventRecord(evG, s1);                                     // router needs A, B
    k_gemm_h<128, 0  ><<<NN / 128, 256, 0, s1>>>(hRF, hWP, hC);   // C = rf @ Wp^T

    // s0: CSR build (concurrent with GEMMs)
    cudaMemsetAsync(degbase, 0, 3 * NN * sizeof(int), 0);
    k_hist<<<(3 * EE / 4 + 255) / 256, 256>>>(pass_dst, connect_dst, transfer_dst);
    k_scan1<<<768, 256>>>();
    k_scan2<<<3, 256>>>();
    k_scan3<<<3 * NN / 256, 256>>>();
    k_fill<<<(3 * EE / 4 + 255) / 256, 256>>>(pass_src, pass_dst, connect_src, connect_dst,
                                              transfer_src, transfer_dst);
    cudaEventRecord(evCSR, 0);

    // s0: router fused gather+epilogue (needs A,B + CSR)
    cudaStreamWaitEvent(0, evG, 0);
    k_gather_router<<<NN * 32 / 256, 256>>>(router_feat, b_r, out);

    // s1: packet fused gather+epilogue (needs C [in-order] + CSR)
    cudaStreamWaitEvent(s1, evCSR, 0);
    k_gather_packet<<<NN * 32 / 256, 256, 0, s1>>>(packet_feat, b_p, out + (size_t)NN * HH);

    // join
    cudaEventRecord(evJoin, s1);
    cudaStreamWaitEvent(0, evJoin, 0);
}